// round 1
// baseline (speedup 1.0000x reference)
#include <cuda_runtime.h>

// Problem shape (fixed by the dataset)
#define BATCH 2
#define SEQ   2048
#define DIM   1024
#define NHEAD 16
#define DHEAD 64
#define MROWS (BATCH * SEQ)          // 4096
#define NQKV  (3 * DIM)              // 3072

// Scratch (allocation-free rule: __device__ globals)
__device__ float g_q[BATCH * NHEAD * SEQ * DHEAD];   // [b,h,s,dh], pre-scaled by 1/8
__device__ float g_k[BATCH * NHEAD * SEQ * DHEAD];
__device__ float g_v[BATCH * NHEAD * SEQ * DHEAD];
__device__ float g_att[BATCH * SEQ * DIM];           // merged-head attention output

// ---------------------------------------------------------------------------
// Kernel 1: QKV GEMM.  C[4096,3072] = X[4096,1024] @ W[1024,3072] + b
// Epilogue scatters into g_q/g_k/g_v in [b,h,s,dh] layout; q scaled by 0.125.
// 64x64 tile, BK=16, 256 threads, 4x4 per thread.
// ---------------------------------------------------------------------------
__global__ __launch_bounds__(256) void qkv_gemm_kernel(
    const float* __restrict__ X, const float* __restrict__ W,
    const float* __restrict__ bias)
{
    __shared__ float As[16][64];
    __shared__ float Bs[16][64];

    const int t  = threadIdx.x;
    const int m0 = blockIdx.y * 64;
    const int n0 = blockIdx.x * 64;
    const int tx = t & 15;
    const int ty = t >> 4;

    const int arow = t >> 2;           // 0..63
    const int acol = (t & 3) << 2;     // 0,4,8,12
    const int brow = t >> 4;           // 0..15
    const int bcol = (t & 15) << 2;    // 0..60

    const float* Aptr = X + (m0 + arow) * DIM + acol;
    const float* Bptr = W + brow * NQKV + n0 + bcol;

    float acc[4][4];
#pragma unroll
    for (int i = 0; i < 4; ++i)
#pragma unroll
        for (int j = 0; j < 4; ++j) acc[i][j] = 0.f;

    for (int kt = 0; kt < DIM / 16; ++kt) {
        float4 a = *(const float4*)(Aptr + kt * 16);
        float4 b = *(const float4*)(Bptr + (size_t)kt * 16 * NQKV);
        As[acol + 0][arow] = a.x;
        As[acol + 1][arow] = a.y;
        As[acol + 2][arow] = a.z;
        As[acol + 3][arow] = a.w;
        *(float4*)&Bs[brow][bcol] = b;
        __syncthreads();

#pragma unroll
        for (int k = 0; k < 16; ++k) {
            float4 av = *(const float4*)&As[k][ty << 2];
            float4 bv = *(const float4*)&Bs[k][tx << 2];
            acc[0][0] += av.x * bv.x; acc[0][1] += av.x * bv.y;
            acc[0][2] += av.x * bv.z; acc[0][3] += av.x * bv.w;
            acc[1][0] += av.y * bv.x; acc[1][1] += av.y * bv.y;
            acc[1][2] += av.y * bv.z; acc[1][3] += av.y * bv.w;
            acc[2][0] += av.z * bv.x; acc[2][1] += av.z * bv.y;
            acc[2][2] += av.z * bv.z; acc[2][3] += av.z * bv.w;
            acc[3][0] += av.w * bv.x; acc[3][1] += av.w * bv.y;
            acc[3][2] += av.w * bv.z; acc[3][3] += av.w * bv.w;
        }
        __syncthreads();
    }

#pragma unroll
    for (int i = 0; i < 4; ++i) {
        const int m = m0 + (ty << 2) + i;
        const int bb = m >> 11;          // batch
        const int s  = m & 2047;         // seq pos
#pragma unroll
        for (int j = 0; j < 4; ++j) {
            const int n = n0 + (tx << 2) + j;
            float v = acc[i][j] + bias[n];
            const int part = n >> 10;    // 0=q 1=k 2=v
            const int dd = n & 1023;
            const int h  = dd >> 6;
            const int hd = dd & 63;
            const int idx = (((bb << 4) + h) * SEQ + s) * DHEAD + hd;
            if (part == 0)      g_q[idx] = v * 0.125f;   // fold 1/sqrt(dh)
            else if (part == 1) g_k[idx] = v;
            else                g_v[idx] = v;
        }
    }
}

// ---------------------------------------------------------------------------
// Kernel 2: causal flash attention, fp32.
// One thread per query row; 64-row query tile per block (64 threads).
// K/V tiles (64x64) in SMEM (broadcast reads); score row staged in SMEM.
// Masked entries use exactly -10000.0f (matches GPT-2 additive mask).
// Output written merged-head into g_att[b, s, h*64+dh].
// ---------------------------------------------------------------------------
__global__ __launch_bounds__(64) void attn_kernel()
{
    __shared__ float4 Ks[64 * 16];       // 16 KB  [key][d4]
    __shared__ float4 Vs[64 * 16];       // 16 KB
    __shared__ float  Ssm[64][64];       // 16 KB  [key][thread]

    const int t    = threadIdx.x;        // 0..63  (query row within tile)
    const int qt   = blockIdx.x;         // query tile (0..31)
    const int bh   = blockIdx.y;         // b*16+h  (0..31)
    const int qrow = qt * 64 + t;

    const float*  Qb = g_q + (size_t)bh * SEQ * DHEAD;
    const float4* Kg = (const float4*)(g_k + (size_t)bh * SEQ * DHEAD);
    const float4* Vg = (const float4*)(g_v + (size_t)bh * SEQ * DHEAD);

    float4 q4[16];
    {
        const float4* qp = (const float4*)(Qb + qrow * DHEAD);
#pragma unroll
        for (int i = 0; i < 16; ++i) q4[i] = qp[i];
    }

    float  mrun = -1e30f, lrun = 0.f;
    float4 o4[16];
#pragma unroll
    for (int i = 0; i < 16; ++i) o4[i] = make_float4(0.f, 0.f, 0.f, 0.f);

    const int ntiles = qt + 1;           // causal: key tiles 0..qt
    for (int kt = 0; kt < ntiles; ++kt) {
        // cooperative load of K/V tile: 1024 float4 by 64 threads
#pragma unroll
        for (int i = 0; i < 16; ++i) {
            Ks[t + i * 64] = Kg[(size_t)kt * 1024 + t + i * 64];
            Vs[t + i * 64] = Vg[(size_t)kt * 1024 + t + i * 64];
        }
        __syncthreads();

        const int kbase = kt * 64;
        float tmax = -1e30f;

        // pass 1: scores (q already carries the 1/8 scale)
#pragma unroll 2
        for (int key = 0; key < 64; ++key) {
            const float4* kr = &Ks[key * 16];
            float acc = 0.f;
#pragma unroll
            for (int d = 0; d < 16; ++d) {
                float4 kv = kr[d];
                acc += q4[d].x * kv.x + q4[d].y * kv.y +
                       q4[d].z * kv.z + q4[d].w * kv.w;
            }
            if (kbase + key > qrow) acc = -10000.0f;
            Ssm[key][t] = acc;
            tmax = fmaxf(tmax, acc);
        }

        const float mnew = fmaxf(mrun, tmax);
        const float corr = __expf(mrun - mnew);
        lrun *= corr;
#pragma unroll
        for (int i = 0; i < 16; ++i) {
            o4[i].x *= corr; o4[i].y *= corr;
            o4[i].z *= corr; o4[i].w *= corr;
        }

        // pass 2: probabilities + PV accumulate
#pragma unroll 2
        for (int key = 0; key < 64; ++key) {
            const float p = __expf(Ssm[key][t] - mnew);
            lrun += p;
            const float4* vr = &Vs[key * 16];
#pragma unroll
            for (int d = 0; d < 16; ++d) {
                float4 vv = vr[d];
                o4[d].x += p * vv.x; o4[d].y += p * vv.y;
                o4[d].z += p * vv.z; o4[d].w += p * vv.w;
            }
        }
        mrun = mnew;
        __syncthreads();
    }

    const float inv = 1.f / lrun;
    const int b = bh >> 4;
    const int h = bh & 15;
    float4* dst = (float4*)(g_att + ((size_t)(b * SEQ + qrow)) * DIM + h * DHEAD);
#pragma unroll
    for (int i = 0; i < 16; ++i) {
        float4 v = o4[i];
        v.x *= inv; v.y *= inv; v.z *= inv; v.w *= inv;
        dst[i] = v;
    }
}

// ---------------------------------------------------------------------------
// Kernel 3: output projection. out[4096,1024] = g_att @ Wp[1024,1024] + bp
// ---------------------------------------------------------------------------
__global__ __launch_bounds__(256) void proj_gemm_kernel(
    const float* __restrict__ Wp, const float* __restrict__ bp,
    float* __restrict__ out)
{
    __shared__ float As[16][64];
    __shared__ float Bs[16][64];

    const int t  = threadIdx.x;
    const int m0 = blockIdx.y * 64;
    const int n0 = blockIdx.x * 64;
    const int tx = t & 15;
    const int ty = t >> 4;

    const int arow = t >> 2;
    const int acol = (t & 3) << 2;
    const int brow = t >> 4;
    const int bcol = (t & 15) << 2;

    const float* Aptr = g_att + (size_t)(m0 + arow) * DIM + acol;
    const float* Bptr = Wp + (size_t)brow * DIM + n0 + bcol;

    float acc[4][4];
#pragma unroll
    for (int i = 0; i < 4; ++i)
#pragma unroll
        for (int j = 0; j < 4; ++j) acc[i][j] = 0.f;

    for (int kt = 0; kt < DIM / 16; ++kt) {
        float4 a = *(const float4*)(Aptr + kt * 16);
        float4 b = *(const float4*)(Bptr + (size_t)kt * 16 * DIM);
        As[acol + 0][arow] = a.x;
        As[acol + 1][arow] = a.y;
        As[acol + 2][arow] = a.z;
        As[acol + 3][arow] = a.w;
        *(float4*)&Bs[brow][bcol] = b;
        __syncthreads();

#pragma unroll
        for (int k = 0; k < 16; ++k) {
            float4 av = *(const float4*)&As[k][ty << 2];
            float4 bv = *(const float4*)&Bs[k][tx << 2];
            acc[0][0] += av.x * bv.x; acc[0][1] += av.x * bv.y;
            acc[0][2] += av.x * bv.z; acc[0][3] += av.x * bv.w;
            acc[1][0] += av.y * bv.x; acc[1][1] += av.y * bv.y;
            acc[1][2] += av.y * bv.z; acc[1][3] += av.y * bv.w;
            acc[2][0] += av.z * bv.x; acc[2][1] += av.z * bv.y;
            acc[2][2] += av.z * bv.z; acc[2][3] += av.z * bv.w;
            acc[3][0] += av.w * bv.x; acc[3][1] += av.w * bv.y;
            acc[3][2] += av.w * bv.z; acc[3][3] += av.w * bv.w;
        }
        __syncthreads();
    }

#pragma unroll
    for (int i = 0; i < 4; ++i) {
        const int m = m0 + (ty << 2) + i;
#pragma unroll
        for (int j = 0; j < 4; ++j) {
            const int n = n0 + (tx << 2) + j;
            out[(size_t)m * DIM + n] = acc[i][j] + bp[n];
        }
    }
}

// ---------------------------------------------------------------------------
extern "C" void kernel_launch(void* const* d_in, const int* in_sizes, int n_in,
                              void* d_out, int out_size)
{
    const float* x      = (const float*)d_in[0];
    const float* w_attn = (const float*)d_in[1];
    const float* b_attn = (const float*)d_in[2];
    const float* w_proj = (const float*)d_in[3];
    const float* b_proj = (const float*)d_in[4];
    float* out = (float*)d_out;

    // 1) QKV GEMM + scatter to [b,h,s,dh]
    qkv_gemm_kernel<<<dim3(NQKV / 64, MROWS / 64), 256>>>(x, w_attn, b_attn);
    // 2) causal flash attention
    attn_kernel<<<dim3(SEQ / 64, BATCH * NHEAD), 64>>>();
    // 3) output projection
    proj_gemm_kernel<<<dim3(DIM / 64, MROWS / 64), 256>>>(w_proj, b_proj, out);
}